// round 2
// baseline (speedup 1.0000x reference)
#include <cuda_runtime.h>

// ---------------------------------------------------------------------------
// PETP_Quadratic: per-element fused-CTP over 4 permutation-equivariant inputs.
//   E = 16384*2*3 = 98304 elements, each with s[32] + v[32][3] features.
//   y_s[w]   = sum_p WSsym[p,w] * F[p]           (F = [s_u s_v pairs, Gram pairs])
//   y_v[w,k] = sum_v (sum_u s_u W23[u,v,w]) v[v,k]
// Weights prescaled by norm = 1/(32*sqrt(2)) (and 1/sqrt(3) for the Gram part).
// ---------------------------------------------------------------------------

#define EDIM        98304
#define NKIND       4
#define WS_PER_KIND (1056*32)   // 33792 floats (528 s-pairs + 528 gram-pairs) x 32 w
#define WV_PER_KIND (32*32*32)  // 32768 floats, layout [v][u][w]
#define NCTA        152
#define EPC         647         // elements per CTA (152*647 = 98344 >= 98304)
#define NWAVE       81          // ceil(647/8)

__device__ float g_WS[NKIND * WS_PER_KIND];
__device__ float g_WV[NKIND * WV_PER_KIND];
__device__ float g_Xk[(size_t)EDIM * NKIND * 128];   // per-element, per-kind features

// ---------------------------------------------------------------------------
// Kernel 1: weight preprocessing.
//   WS[t][p][w]      : p<528 -> sym(W0) pairs * norm ; p>=528 -> sym(W1)*norm/sqrt3
//   WV[t][v][u][w]   = norm * (W2[u][v][w] + W3[v][u][w])
// ---------------------------------------------------------------------------
__global__ void prep_weights(const float* __restrict__ Ws, const float* __restrict__ Wf,
                             const float* __restrict__ Wn, const float* __restrict__ Wa) {
    int tid = blockIdx.x * blockDim.x + threadIdx.x;   // 0..131071
    int w = tid & 31;
    int v = (tid >> 5) & 31;
    int u = (tid >> 10) & 31;
    int t = tid >> 15;
    const float* Wt = (t == 0) ? Ws : (t == 1) ? Wf : (t == 2) ? Wn : Wa;
    const float norm = 0.022097086912079608f;   // 1/(32*sqrt(2))
    const float i3   = 0.5773502691896258f;     // 1/sqrt(3)

    // combined vector weight
    float w2 = Wt[2*32768 + (u*32 + v)*32 + w];
    float w3 = Wt[3*32768 + (v*32 + u)*32 + w];
    g_WV[t*WV_PER_KIND + (v*32 + u)*32 + w] = norm * (w2 + w3);

    // symmetrized scalar/gram weights (upper triangle incl. diagonal)
    if (u <= v) {
        int p = ((u * (65 - u)) >> 1) + (v - u);
        float a0 = Wt[0*32768 + (u*32 + v)*32 + w];
        float a1 = Wt[1*32768 + (u*32 + v)*32 + w];
        if (u != v) {
            a0 += Wt[0*32768 + (v*32 + u)*32 + w];
            a1 += Wt[1*32768 + (v*32 + u)*32 + w];
        }
        g_WS[t*WS_PER_KIND + p*32 + w]         = norm * a0;
        g_WS[t*WS_PER_KIND + (528 + p)*32 + w] = norm * i3 * a1;
    }
}

// ---------------------------------------------------------------------------
// Kernel 2: permutation-equivariant feature construction.
//   one block per batch group b (6 elements), one thread per channel.
// ---------------------------------------------------------------------------
__global__ void prep_features(const float* __restrict__ x) {
    int b  = blockIdx.x;     // 0..16383
    int ch = threadIdx.x;    // 0..127
    const float* xb = x + (size_t)b * 6 * 128 + ch;

    float xv[6];
    #pragma unroll
    for (int q = 0; q < 6; q++) xv[q] = xb[q * 128];

    float r0 = xv[0] + xv[1] + xv[2];
    float r1 = xv[3] + xv[4] + xv[5];
    float c0 = xv[0] + xv[3];
    float c1 = xv[1] + xv[4];
    float c2 = xv[2] + xv[5];
    float tot = r0 + r1;

    float* o = g_Xk + (size_t)b * 6 * 4 * 128 + ch;
    #pragma unroll
    for (int i = 0; i < 2; i++) {
        float ri = i ? r1 : r0;
        #pragma unroll
        for (int j = 0; j < 3; j++) {
            float cj = (j == 0) ? c0 : (j == 1) ? c1 : c2;
            float xs = xv[i*3 + j];
            float xf = (ri - xs) * 0.5f;                 // /(3-1)
            float xn = (cj - xs);                        // /(2-1)
            float xa = (tot - ri - cj + xs) * 0.5f;      // /((2-1)*(3-1))
            float* oe = o + (size_t)(i*3 + j) * 512;
            oe[0]   = xs;
            oe[128] = xf;
            oe[256] = xn;
            oe[384] = xa;
        }
    }
}

// ---------------------------------------------------------------------------
// Kernel 3: main contraction. 8 warps/CTA, warp = element, lane = w channel.
// For each kind t: stage WS[t] (135KB) in smem -> y_s phase over all elements;
// stage WV[t] (128KB) -> y_v phase. Accumulate into out across kinds.
// ---------------------------------------------------------------------------
__global__ void __launch_bounds__(256, 1) petp_main(float* __restrict__ out) {
    extern __shared__ float sm[];
    float* Wsm     = sm;                          // 33792 floats max
    float* featAll = sm + WS_PER_KIND;            // 8 * 128
    float* PGAll   = featAll + 8 * 128;           // 8 * 1056

    const int warp = threadIdx.x >> 5;
    const int lane = threadIdx.x & 31;
    float* feat = featAll + warp * 128;
    float* PG   = PGAll   + warp * 1056;

    const int base = blockIdx.x * EPC;
    const int elim = (base + EPC < EDIM) ? base + EPC : EDIM;

    for (int t = 0; t < 4; t++) {
        // ================= scalar phase =================
        {
            const float4* src = (const float4*)(g_WS + t * WS_PER_KIND);
            float4* dst = (float4*)Wsm;
            for (int i = threadIdx.x; i < WS_PER_KIND / 4; i += 256) dst[i] = src[i];
        }
        __syncthreads();

        for (int wv = 0; wv < NWAVE; wv++) {
            int e = base + wv * 8 + warp;
            if (e < elim) {
                ((float4*)feat)[lane] = ((const float4*)(g_Xk + ((size_t)e*4 + t)*128))[lane];
                __syncwarp();
                // build pair features: lane = u, loop v >= u
                {
                    int u = lane;
                    float su  = feat[u];
                    float va0 = feat[32 + u*3], va1 = feat[33 + u*3], va2 = feat[34 + u*3];
                    int p = (u * (65 - u)) >> 1;
                    for (int v = u; v < 32; ++v, ++p) {
                        PG[p]       = su * feat[v];
                        PG[528 + p] = va0*feat[32 + v*3] + va1*feat[33 + v*3] + va2*feat[34 + v*3];
                    }
                }
                __syncwarp();
                // contract against WS (lane = output w)
                float a0 = 0.f, a1 = 0.f, a2 = 0.f, a3 = 0.f;
                #pragma unroll 4
                for (int p = 0; p < 1056; p += 4) {
                    a0 = fmaf(Wsm[(p+0)*32 + lane], PG[p+0], a0);
                    a1 = fmaf(Wsm[(p+1)*32 + lane], PG[p+1], a1);
                    a2 = fmaf(Wsm[(p+2)*32 + lane], PG[p+2], a2);
                    a3 = fmaf(Wsm[(p+3)*32 + lane], PG[p+3], a3);
                }
                float ys = (a0 + a1) + (a2 + a3);
                float* o = out + (size_t)e * 128 + lane;
                *o = (t == 0) ? ys : (*o + ys);
            }
            __syncwarp();
        }
        __syncthreads();

        // ================= vector phase =================
        {
            const float4* src = (const float4*)(g_WV + t * WV_PER_KIND);
            float4* dst = (float4*)Wsm;
            for (int i = threadIdx.x; i < WV_PER_KIND / 4; i += 256) dst[i] = src[i];
        }
        __syncthreads();

        for (int wv = 0; wv < NWAVE; wv++) {
            int e = base + wv * 8 + warp;
            if (e < elim) {
                ((float4*)feat)[lane] = ((const float4*)(g_Xk + ((size_t)e*4 + t)*128))[lane];
                __syncwarp();
                // c[v] = sum_u s_u * WV[v][u][lane]
                float c[32];
                #pragma unroll
                for (int v = 0; v < 32; v++) c[v] = 0.f;
                #pragma unroll 4
                for (int u = 0; u < 32; ++u) {
                    float su = feat[u];
                    #pragma unroll
                    for (int v = 0; v < 32; ++v)
                        c[v] = fmaf(su, Wsm[v*1024 + u*32 + lane], c[v]);
                }
                // y_v[lane][k] = sum_v c[v] * v[v][k]
                float y0 = 0.f, y1 = 0.f, y2 = 0.f;
                #pragma unroll
                for (int v = 0; v < 32; ++v) {
                    float cv = c[v];
                    y0 = fmaf(cv, feat[32 + v*3], y0);
                    y1 = fmaf(cv, feat[33 + v*3], y1);
                    y2 = fmaf(cv, feat[34 + v*3], y2);
                }
                float* o = out + (size_t)e * 128 + 32 + lane * 3;
                if (t == 0) { o[0] = y0;       o[1] = y1;       o[2] = y2; }
                else        { o[0] += y0;      o[1] += y1;      o[2] += y2; }
            }
            __syncwarp();
        }
        __syncthreads();
    }
}

// ---------------------------------------------------------------------------
extern "C" void kernel_launch(void* const* d_in, const int* in_sizes, int n_in,
                              void* d_out, int out_size) {
    const float* x  = (const float*)d_in[0];
    const float* Ws = (const float*)d_in[1];
    const float* Wf = (const float*)d_in[2];
    const float* Wn = (const float*)d_in[3];
    const float* Wa = (const float*)d_in[4];

    const int smem_bytes = (WS_PER_KIND + 8*128 + 8*1056) * 4;   // 173056
    cudaFuncSetAttribute(petp_main, cudaFuncAttributeMaxDynamicSharedMemorySize, smem_bytes);

    prep_weights<<<512, 256>>>(Ws, Wf, Wn, Wa);
    prep_features<<<16384, 128>>>(x);
    petp_main<<<NCTA, 256, smem_bytes>>>((float*)d_out);
}

// round 3
// speedup vs baseline: 2.0069x; 2.0069x over previous
#include <cuda_runtime.h>

// ---------------------------------------------------------------------------
// PETP_Quadratic v2: 4-element-per-warp register/LDS.128 blocked CTP.
//   y_s[w]   = sum_p WS[p,w] * PG[p]       (PG = 528 s-pairs + 528 gram pairs)
//   y_v[w,k] = sum_v (sum_u s_u WV[u,v,w]) v[v,k]
// ---------------------------------------------------------------------------

#define EDIM  98304
#define NPAIR 528
#define WS_FLOATS (1056*32)       // 33792, layout [p/4][w][4]
#define WV_FLOATS (32*32*36)      // 36864, layout [u][w][v pad 36]
#define NCTA   148
#define EPC    665                // 148*665 = 98420 >= 98304
#define NWARPS 16
#define CH     88                 // pairs per build chunk, 528 = 6*88
#define NCHUNK 6

__device__ float g_WS[4 * WS_FLOATS];
__device__ float g_WV[4 * WV_FLOATS];
__device__ unsigned short g_LUT[NPAIR];
__device__ float g_Xk[(size_t)EDIM * 4 * 128];

// ---------------------------------------------------------------------------
// Prep: blocks [0,1024) do weights, blocks [1024, 17408) do features.
// ---------------------------------------------------------------------------
__global__ void prep(const float* __restrict__ x,
                     const float* __restrict__ Ws, const float* __restrict__ Wf,
                     const float* __restrict__ Wn, const float* __restrict__ Wa) {
    int blk = blockIdx.x;
    if (blk < 1024) {
        int tid = blk * 128 + threadIdx.x;        // 0..131071
        int w = tid & 31;
        int v = (tid >> 5) & 31;
        int u = (tid >> 10) & 31;
        int t = tid >> 15;
        const float* Wt = (t == 0) ? Ws : (t == 1) ? Wf : (t == 2) ? Wn : Wa;
        const float norm = 0.022097086912079608f;   // 1/(32*sqrt(2))
        const float i3   = 0.5773502691896258f;     // 1/sqrt(3)

        float w2 = Wt[2*32768 + (u*32 + v)*32 + w];
        float w3 = Wt[3*32768 + (v*32 + u)*32 + w];
        g_WV[t*WV_FLOATS + u*1152 + w*36 + v] = norm * (w2 + w3);

        if (u <= v) {
            int p = ((u * (65 - u)) >> 1) + (v - u);
            float a0 = Wt[0*32768 + (u*32 + v)*32 + w];
            float a1 = Wt[1*32768 + (u*32 + v)*32 + w];
            if (u != v) {
                a0 += Wt[0*32768 + (v*32 + u)*32 + w];
                a1 += Wt[1*32768 + (v*32 + u)*32 + w];
            }
            int q  = p;
            int q2 = 528 + p;
            g_WS[t*WS_FLOATS + (q  >> 2)*128 + w*4 + (q  & 3)] = norm * a0;
            g_WS[t*WS_FLOATS + (q2 >> 2)*128 + w*4 + (q2 & 3)] = norm * i3 * a1;
            if (t == 0 && w == 0) g_LUT[p] = (unsigned short)(u | (v << 8));
        }
    } else {
        int b  = blk - 1024;     // 0..16383
        int ch = threadIdx.x;    // 0..127
        const float* xb = x + (size_t)b * 6 * 128 + ch;
        float xv[6];
        #pragma unroll
        for (int q = 0; q < 6; q++) xv[q] = xb[q * 128];
        float r0 = xv[0] + xv[1] + xv[2];
        float r1 = xv[3] + xv[4] + xv[5];
        float c0 = xv[0] + xv[3];
        float c1 = xv[1] + xv[4];
        float c2 = xv[2] + xv[5];
        float tot = r0 + r1;
        float* o = g_Xk + (size_t)b * 6 * 4 * 128 + ch;
        #pragma unroll
        for (int i = 0; i < 2; i++) {
            float ri = i ? r1 : r0;
            #pragma unroll
            for (int j = 0; j < 3; j++) {
                float cj = (j == 0) ? c0 : (j == 1) ? c1 : c2;
                float xs = xv[i*3 + j];
                float xf = (ri - xs) * 0.5f;
                float xn = (cj - xs);
                float xa = (tot - ri - cj + xs) * 0.5f;
                float* oe = o + (size_t)(i*3 + j) * 512;
                oe[0]   = xs;
                oe[128] = xf;
                oe[256] = xn;
                oe[384] = xa;
            }
        }
    }
}

// ---------------------------------------------------------------------------
// Main: 148 CTAs x 512 threads. Warp processes 4 elements at a time.
// ---------------------------------------------------------------------------
__global__ void __launch_bounds__(512, 1) petp_main(float* __restrict__ out) {
    extern __shared__ float sm[];
    float* Wsm     = sm;                                   // 36864 floats max
    float* PGall   = sm + WV_FLOATS;                       // 16 * 4 * 88
    float* featall = PGall + NWARPS * 4 * CH;              // 16 * 512
    float* S4all   = featall + NWARPS * 512;               // 16 * 128
    unsigned short* LUTs = (unsigned short*)(S4all + NWARPS * 128);  // 528 u16

    const int tid  = threadIdx.x;
    const int warp = tid >> 5;
    const int lane = tid & 31;
    float* PG   = PGall   + warp * 4 * CH;
    float* feat = featall + warp * 512;
    float* S4   = S4all   + warp * 128;

    for (int i = tid; i < NPAIR; i += 512) LUTs[i] = g_LUT[i];

    const int base  = blockIdx.x * EPC;
    const int count = (EPC < EDIM - base) ? EPC : (EDIM - base);

    for (int t = 0; t < 4; ++t) {
        // ================= scalar phase =================
        __syncthreads();
        {
            const float4* src = (const float4*)(g_WS + t * WS_FLOATS);
            float4* dst = (float4*)Wsm;
            for (int i = tid; i < WS_FLOATS/4; i += 512) dst[i] = src[i];
        }
        __syncthreads();

        for (int g = warp; g * 4 < count; g += NWARPS) {
            const int e0 = base + g * 4;
            #pragma unroll
            for (int e = 0; e < 4; ++e) {
                int ee = e0 + e; if (ee >= EDIM) ee = EDIM - 1;
                ((float4*)(feat + e*128))[lane] =
                    ((const float4*)(g_Xk + ((size_t)ee*4 + t)*128))[lane];
            }
            __syncwarp();

            float a0_0=0.f,a0_1=0.f,a0_2=0.f,a0_3=0.f;
            float a1_0=0.f,a1_1=0.f,a1_2=0.f,a1_3=0.f;

            #pragma unroll 1
            for (int h = 0; h < 2; ++h) {
                #pragma unroll 1
                for (int c = 0; c < NCHUNK; ++c) {
                    const int p0 = c * CH;
                    // ---- build chunk ----
                    for (int i = lane; i < CH; i += 32) {
                        unsigned int uv = LUTs[p0 + i];
                        int u = uv & 255, v = uv >> 8;
                        if (h == 0) {
                            #pragma unroll
                            for (int e = 0; e < 4; ++e)
                                PG[e*CH + i] = feat[e*128 + u] * feat[e*128 + v];
                        } else {
                            #pragma unroll
                            for (int e = 0; e < 4; ++e) {
                                const float* fu = feat + e*128 + 32 + u*3;
                                const float* fv = feat + e*128 + 32 + v*3;
                                PG[e*CH + i] = fmaf(fu[0], fv[0],
                                                fmaf(fu[1], fv[1], fu[2]*fv[2]));
                            }
                        }
                    }
                    __syncwarp();
                    // ---- contract chunk ----
                    const int pb0 = (h * 528 + p0) >> 2;
                    const float4* W4  = (const float4*)Wsm;
                    const float4* P0  = (const float4*)(PG);
                    const float4* P1  = (const float4*)(PG + CH);
                    const float4* P2  = (const float4*)(PG + 2*CH);
                    const float4* P3  = (const float4*)(PG + 3*CH);
                    #pragma unroll 2
                    for (int b = 0; b < CH/4; ++b) {
                        float4 wv = W4[(pb0 + b)*32 + lane];
                        float4 f0 = P0[b], f1 = P1[b], f2 = P2[b], f3 = P3[b];
                        a0_0 = fmaf(wv.x, f0.x, a0_0); a1_0 = fmaf(wv.y, f0.y, a1_0);
                        a0_0 = fmaf(wv.z, f0.z, a0_0); a1_0 = fmaf(wv.w, f0.w, a1_0);
                        a0_1 = fmaf(wv.x, f1.x, a0_1); a1_1 = fmaf(wv.y, f1.y, a1_1);
                        a0_1 = fmaf(wv.z, f1.z, a0_1); a1_1 = fmaf(wv.w, f1.w, a1_1);
                        a0_2 = fmaf(wv.x, f2.x, a0_2); a1_2 = fmaf(wv.y, f2.y, a1_2);
                        a0_2 = fmaf(wv.z, f2.z, a0_2); a1_2 = fmaf(wv.w, f2.w, a1_2);
                        a0_3 = fmaf(wv.x, f3.x, a0_3); a1_3 = fmaf(wv.y, f3.y, a1_3);
                        a0_3 = fmaf(wv.z, f3.z, a0_3); a1_3 = fmaf(wv.w, f3.w, a1_3);
                    }
                    __syncwarp();
                }
            }
            float ys[4] = { a0_0 + a1_0, a0_1 + a1_1, a0_2 + a1_2, a0_3 + a1_3 };
            #pragma unroll
            for (int e = 0; e < 4; ++e) {
                if (g*4 + e < count) {
                    float* o = out + (size_t)(e0 + e)*128 + lane;
                    *o = (t == 0) ? ys[e] : (*o + ys[e]);
                }
            }
        }

        // ================= vector phase =================
        __syncthreads();
        {
            const float4* src = (const float4*)(g_WV + t * WV_FLOATS);
            float4* dst = (float4*)Wsm;
            for (int i = tid; i < WV_FLOATS/4; i += 512) dst[i] = src[i];
        }
        __syncthreads();

        for (int g = warp; g * 4 < count; g += NWARPS) {
            const int e0 = base + g * 4;
            #pragma unroll
            for (int e = 0; e < 4; ++e) {
                int ee = e0 + e; if (ee >= EDIM) ee = EDIM - 1;
                ((float4*)(feat + e*128))[lane] =
                    ((const float4*)(g_Xk + ((size_t)ee*4 + t)*128))[lane];
            }
            __syncwarp();
            #pragma unroll
            for (int e = 0; e < 4; ++e) S4[lane*4 + e] = feat[e*128 + lane];
            __syncwarp();

            float y0[4] = {0,0,0,0}, y1[4] = {0,0,0,0}, y2[4] = {0,0,0,0};

            #pragma unroll 1
            for (int vc = 0; vc < 32; vc += 8) {
                float cacc[8][4];
                #pragma unroll
                for (int j = 0; j < 8; ++j)
                    #pragma unroll
                    for (int e = 0; e < 4; ++e) cacc[j][e] = 0.f;

                #pragma unroll 4
                for (int u = 0; u < 32; ++u) {
                    float4 s4v = *((const float4*)(S4 + u*4));                     // uniform
                    float4 wA  = *((const float4*)(Wsm + u*1152 + lane*36 + vc));
                    float4 wB  = *((const float4*)(Wsm + u*1152 + lane*36 + vc + 4));
                    float sA[4] = { s4v.x, s4v.y, s4v.z, s4v.w };
                    float wAa[4] = { wA.x, wA.y, wA.z, wA.w };
                    float wBa[4] = { wB.x, wB.y, wB.z, wB.w };
                    #pragma unroll
                    for (int j = 0; j < 4; ++j)
                        #pragma unroll
                        for (int e = 0; e < 4; ++e) {
                            cacc[j][e]   = fmaf(wAa[j], sA[e], cacc[j][e]);
                            cacc[4+j][e] = fmaf(wBa[j], sA[e], cacc[4+j][e]);
                        }
                }
                #pragma unroll
                for (int j = 0; j < 8; ++j) {
                    const int v = vc + j;
                    #pragma unroll
                    for (int e = 0; e < 4; ++e) {
                        float cv = cacc[j][e];
                        const float* fv = feat + e*128 + 32 + v*3;   // uniform
                        y0[e] = fmaf(cv, fv[0], y0[e]);
                        y1[e] = fmaf(cv, fv[1], y1[e]);
                        y2[e] = fmaf(cv, fv[2], y2[e]);
                    }
                }
            }
            #pragma unroll
            for (int e = 0; e < 4; ++e) {
                if (g*4 + e < count) {
                    float* o = out + (size_t)(e0 + e)*128 + 32 + lane*3;
                    if (t == 0) { o[0] = y0[e];  o[1] = y1[e];  o[2] = y2[e]; }
                    else        { o[0] += y0[e]; o[1] += y1[e]; o[2] += y2[e]; }
                }
            }
        }
    }
}

// ---------------------------------------------------------------------------
extern "C" void kernel_launch(void* const* d_in, const int* in_sizes, int n_in,
                              void* d_out, int out_size) {
    const float* x  = (const float*)d_in[0];
    const float* Ws = (const float*)d_in[1];
    const float* Wf = (const float*)d_in[2];
    const float* Wn = (const float*)d_in[3];
    const float* Wa = (const float*)d_in[4];

    const int smem_floats = WV_FLOATS + NWARPS*4*CH + NWARPS*512 + NWARPS*128 + 264;
    const int smem_bytes  = smem_floats * 4;   // ~212 KB
    cudaFuncSetAttribute(petp_main, cudaFuncAttributeMaxDynamicSharedMemorySize, smem_bytes);

    prep<<<17408, 128>>>(x, Ws, Wf, Wn, Wa);
    petp_main<<<NCTA, 512, smem_bytes>>>((float*)d_out);
}

// round 4
// speedup vs baseline: 2.0084x; 1.0007x over previous
#include <cuda_runtime.h>

// ---------------------------------------------------------------------------
// PETP_Quadratic v2: 4-element-per-warp register/LDS.128 blocked CTP.
//   y_s[w]   = sum_p WS[p,w] * PG[p]       (PG = 528 s-pairs + 528 gram pairs)
//   y_v[w,k] = sum_v (sum_u s_u WV[u,v,w]) v[v,k]
// ---------------------------------------------------------------------------

#define EDIM  98304
#define NPAIR 528
#define WS_FLOATS (1056*32)       // 33792, layout [p/4][w][4]
#define WV_FLOATS (32*32*36)      // 36864, layout [u][w][v pad 36]
#define NCTA   148
#define EPC    665                // 148*665 = 98420 >= 98304
#define NWARPS 16
#define CH     88                 // pairs per build chunk, 528 = 6*88
#define NCHUNK 6

__device__ float g_WS[4 * WS_FLOATS];
__device__ float g_WV[4 * WV_FLOATS];
__device__ unsigned short g_LUT[NPAIR];
__device__ float g_Xk[(size_t)EDIM * 4 * 128];

// ---------------------------------------------------------------------------
// Prep: blocks [0,1024) do weights, blocks [1024, 17408) do features.
// ---------------------------------------------------------------------------
__global__ void prep(const float* __restrict__ x,
                     const float* __restrict__ Ws, const float* __restrict__ Wf,
                     const float* __restrict__ Wn, const float* __restrict__ Wa) {
    int blk = blockIdx.x;
    if (blk < 1024) {
        int tid = blk * 128 + threadIdx.x;        // 0..131071
        int w = tid & 31;
        int v = (tid >> 5) & 31;
        int u = (tid >> 10) & 31;
        int t = tid >> 15;
        const float* Wt = (t == 0) ? Ws : (t == 1) ? Wf : (t == 2) ? Wn : Wa;
        const float norm = 0.022097086912079608f;   // 1/(32*sqrt(2))
        const float i3   = 0.5773502691896258f;     // 1/sqrt(3)

        float w2 = Wt[2*32768 + (u*32 + v)*32 + w];
        float w3 = Wt[3*32768 + (v*32 + u)*32 + w];
        g_WV[t*WV_FLOATS + u*1152 + w*36 + v] = norm * (w2 + w3);

        if (u <= v) {
            int p = ((u * (65 - u)) >> 1) + (v - u);
            float a0 = Wt[0*32768 + (u*32 + v)*32 + w];
            float a1 = Wt[1*32768 + (u*32 + v)*32 + w];
            if (u != v) {
                a0 += Wt[0*32768 + (v*32 + u)*32 + w];
                a1 += Wt[1*32768 + (v*32 + u)*32 + w];
            }
            int q  = p;
            int q2 = 528 + p;
            g_WS[t*WS_FLOATS + (q  >> 2)*128 + w*4 + (q  & 3)] = norm * a0;
            g_WS[t*WS_FLOATS + (q2 >> 2)*128 + w*4 + (q2 & 3)] = norm * i3 * a1;
            if (t == 0 && w == 0) g_LUT[p] = (unsigned short)(u | (v << 8));
        }
    } else {
        int b  = blk - 1024;     // 0..16383
        int ch = threadIdx.x;    // 0..127
        const float* xb = x + (size_t)b * 6 * 128 + ch;
        float xv[6];
        #pragma unroll
        for (int q = 0; q < 6; q++) xv[q] = xb[q * 128];
        float r0 = xv[0] + xv[1] + xv[2];
        float r1 = xv[3] + xv[4] + xv[5];
        float c0 = xv[0] + xv[3];
        float c1 = xv[1] + xv[4];
        float c2 = xv[2] + xv[5];
        float tot = r0 + r1;
        float* o = g_Xk + (size_t)b * 6 * 4 * 128 + ch;
        #pragma unroll
        for (int i = 0; i < 2; i++) {
            float ri = i ? r1 : r0;
            #pragma unroll
            for (int j = 0; j < 3; j++) {
                float cj = (j == 0) ? c0 : (j == 1) ? c1 : c2;
                float xs = xv[i*3 + j];
                float xf = (ri - xs) * 0.5f;
                float xn = (cj - xs);
                float xa = (tot - ri - cj + xs) * 0.5f;
                float* oe = o + (size_t)(i*3 + j) * 512;
                oe[0]   = xs;
                oe[128] = xf;
                oe[256] = xn;
                oe[384] = xa;
            }
        }
    }
}

// ---------------------------------------------------------------------------
// Main: 148 CTAs x 512 threads. Warp processes 4 elements at a time.
// ---------------------------------------------------------------------------
__global__ void __launch_bounds__(512, 1) petp_main(float* __restrict__ out) {
    extern __shared__ float sm[];
    float* Wsm     = sm;                                   // 36864 floats max
    float* PGall   = sm + WV_FLOATS;                       // 16 * 4 * 88
    float* featall = PGall + NWARPS * 4 * CH;              // 16 * 512
    float* S4all   = featall + NWARPS * 512;               // 16 * 128
    unsigned short* LUTs = (unsigned short*)(S4all + NWARPS * 128);  // 528 u16

    const int tid  = threadIdx.x;
    const int warp = tid >> 5;
    const int lane = tid & 31;
    float* PG   = PGall   + warp * 4 * CH;
    float* feat = featall + warp * 512;
    float* S4   = S4all   + warp * 128;

    for (int i = tid; i < NPAIR; i += 512) LUTs[i] = g_LUT[i];

    const int base  = blockIdx.x * EPC;
    const int count = (EPC < EDIM - base) ? EPC : (EDIM - base);

    for (int t = 0; t < 4; ++t) {
        // ================= scalar phase =================
        __syncthreads();
        {
            const float4* src = (const float4*)(g_WS + t * WS_FLOATS);
            float4* dst = (float4*)Wsm;
            for (int i = tid; i < WS_FLOATS/4; i += 512) dst[i] = src[i];
        }
        __syncthreads();

        for (int g = warp; g * 4 < count; g += NWARPS) {
            const int e0 = base + g * 4;
            #pragma unroll
            for (int e = 0; e < 4; ++e) {
                int ee = e0 + e; if (ee >= EDIM) ee = EDIM - 1;
                ((float4*)(feat + e*128))[lane] =
                    ((const float4*)(g_Xk + ((size_t)ee*4 + t)*128))[lane];
            }
            __syncwarp();

            float a0_0=0.f,a0_1=0.f,a0_2=0.f,a0_3=0.f;
            float a1_0=0.f,a1_1=0.f,a1_2=0.f,a1_3=0.f;

            #pragma unroll 1
            for (int h = 0; h < 2; ++h) {
                #pragma unroll 1
                for (int c = 0; c < NCHUNK; ++c) {
                    const int p0 = c * CH;
                    // ---- build chunk ----
                    for (int i = lane; i < CH; i += 32) {
                        unsigned int uv = LUTs[p0 + i];
                        int u = uv & 255, v = uv >> 8;
                        if (h == 0) {
                            #pragma unroll
                            for (int e = 0; e < 4; ++e)
                                PG[e*CH + i] = feat[e*128 + u] * feat[e*128 + v];
                        } else {
                            #pragma unroll
                            for (int e = 0; e < 4; ++e) {
                                const float* fu = feat + e*128 + 32 + u*3;
                                const float* fv = feat + e*128 + 32 + v*3;
                                PG[e*CH + i] = fmaf(fu[0], fv[0],
                                                fmaf(fu[1], fv[1], fu[2]*fv[2]));
                            }
                        }
                    }
                    __syncwarp();
                    // ---- contract chunk ----
                    const int pb0 = (h * 528 + p0) >> 2;
                    const float4* W4  = (const float4*)Wsm;
                    const float4* P0  = (const float4*)(PG);
                    const float4* P1  = (const float4*)(PG + CH);
                    const float4* P2  = (const float4*)(PG + 2*CH);
                    const float4* P3  = (const float4*)(PG + 3*CH);
                    #pragma unroll 2
                    for (int b = 0; b < CH/4; ++b) {
                        float4 wv = W4[(pb0 + b)*32 + lane];
                        float4 f0 = P0[b], f1 = P1[b], f2 = P2[b], f3 = P3[b];
                        a0_0 = fmaf(wv.x, f0.x, a0_0); a1_0 = fmaf(wv.y, f0.y, a1_0);
                        a0_0 = fmaf(wv.z, f0.z, a0_0); a1_0 = fmaf(wv.w, f0.w, a1_0);
                        a0_1 = fmaf(wv.x, f1.x, a0_1); a1_1 = fmaf(wv.y, f1.y, a1_1);
                        a0_1 = fmaf(wv.z, f1.z, a0_1); a1_1 = fmaf(wv.w, f1.w, a1_1);
                        a0_2 = fmaf(wv.x, f2.x, a0_2); a1_2 = fmaf(wv.y, f2.y, a1_2);
                        a0_2 = fmaf(wv.z, f2.z, a0_2); a1_2 = fmaf(wv.w, f2.w, a1_2);
                        a0_3 = fmaf(wv.x, f3.x, a0_3); a1_3 = fmaf(wv.y, f3.y, a1_3);
                        a0_3 = fmaf(wv.z, f3.z, a0_3); a1_3 = fmaf(wv.w, f3.w, a1_3);
                    }
                    __syncwarp();
                }
            }
            float ys[4] = { a0_0 + a1_0, a0_1 + a1_1, a0_2 + a1_2, a0_3 + a1_3 };
            #pragma unroll
            for (int e = 0; e < 4; ++e) {
                if (g*4 + e < count) {
                    float* o = out + (size_t)(e0 + e)*128 + lane;
                    *o = (t == 0) ? ys[e] : (*o + ys[e]);
                }
            }
        }

        // ================= vector phase =================
        __syncthreads();
        {
            const float4* src = (const float4*)(g_WV + t * WV_FLOATS);
            float4* dst = (float4*)Wsm;
            for (int i = tid; i < WV_FLOATS/4; i += 512) dst[i] = src[i];
        }
        __syncthreads();

        for (int g = warp; g * 4 < count; g += NWARPS) {
            const int e0 = base + g * 4;
            #pragma unroll
            for (int e = 0; e < 4; ++e) {
                int ee = e0 + e; if (ee >= EDIM) ee = EDIM - 1;
                ((float4*)(feat + e*128))[lane] =
                    ((const float4*)(g_Xk + ((size_t)ee*4 + t)*128))[lane];
            }
            __syncwarp();
            #pragma unroll
            for (int e = 0; e < 4; ++e) S4[lane*4 + e] = feat[e*128 + lane];
            __syncwarp();

            float y0[4] = {0,0,0,0}, y1[4] = {0,0,0,0}, y2[4] = {0,0,0,0};

            #pragma unroll 1
            for (int vc = 0; vc < 32; vc += 8) {
                float cacc[8][4];
                #pragma unroll
                for (int j = 0; j < 8; ++j)
                    #pragma unroll
                    for (int e = 0; e < 4; ++e) cacc[j][e] = 0.f;

                #pragma unroll 4
                for (int u = 0; u < 32; ++u) {
                    float4 s4v = *((const float4*)(S4 + u*4));                     // uniform
                    float4 wA  = *((const float4*)(Wsm + u*1152 + lane*36 + vc));
                    float4 wB  = *((const float4*)(Wsm + u*1152 + lane*36 + vc + 4));
                    float sA[4] = { s4v.x, s4v.y, s4v.z, s4v.w };
                    float wAa[4] = { wA.x, wA.y, wA.z, wA.w };
                    float wBa[4] = { wB.x, wB.y, wB.z, wB.w };
                    #pragma unroll
                    for (int j = 0; j < 4; ++j)
                        #pragma unroll
                        for (int e = 0; e < 4; ++e) {
                            cacc[j][e]   = fmaf(wAa[j], sA[e], cacc[j][e]);
                            cacc[4+j][e] = fmaf(wBa[j], sA[e], cacc[4+j][e]);
                        }
                }
                #pragma unroll
                for (int j = 0; j < 8; ++j) {
                    const int v = vc + j;
                    #pragma unroll
                    for (int e = 0; e < 4; ++e) {
                        float cv = cacc[j][e];
                        const float* fv = feat + e*128 + 32 + v*3;   // uniform
                        y0[e] = fmaf(cv, fv[0], y0[e]);
                        y1[e] = fmaf(cv, fv[1], y1[e]);
                        y2[e] = fmaf(cv, fv[2], y2[e]);
                    }
                }
            }
            #pragma unroll
            for (int e = 0; e < 4; ++e) {
                if (g*4 + e < count) {
                    float* o = out + (size_t)(e0 + e)*128 + 32 + lane*3;
                    if (t == 0) { o[0] = y0[e];  o[1] = y1[e];  o[2] = y2[e]; }
                    else        { o[0] += y0[e]; o[1] += y1[e]; o[2] += y2[e]; }
                }
            }
        }
    }
}

// ---------------------------------------------------------------------------
extern "C" void kernel_launch(void* const* d_in, const int* in_sizes, int n_in,
                              void* d_out, int out_size) {
    const float* x  = (const float*)d_in[0];
    const float* Ws = (const float*)d_in[1];
    const float* Wf = (const float*)d_in[2];
    const float* Wn = (const float*)d_in[3];
    const float* Wa = (const float*)d_in[4];

    const int smem_floats = WV_FLOATS + NWARPS*4*CH + NWARPS*512 + NWARPS*128 + 264;
    const int smem_bytes  = smem_floats * 4;   // ~212 KB
    cudaFuncSetAttribute(petp_main, cudaFuncAttributeMaxDynamicSharedMemorySize, smem_bytes);

    prep<<<17408, 128>>>(x, Ws, Wf, Wn, Wa);
    petp_main<<<NCTA, 512, smem_bytes>>>((float*)d_out);
}

// round 5
// speedup vs baseline: 2.0093x; 1.0005x over previous
#include <cuda_runtime.h>

// ---------------------------------------------------------------------------
// PETP_Quadratic v2: 4-element-per-warp register/LDS.128 blocked CTP.
//   y_s[w]   = sum_p WS[p,w] * PG[p]       (PG = 528 s-pairs + 528 gram pairs)
//   y_v[w,k] = sum_v (sum_u s_u WV[u,v,w]) v[v,k]
// ---------------------------------------------------------------------------

#define EDIM  98304
#define NPAIR 528
#define WS_FLOATS (1056*32)       // 33792, layout [p/4][w][4]
#define WV_FLOATS (32*32*36)      // 36864, layout [u][w][v pad 36]
#define NCTA   148
#define EPC    665                // 148*665 = 98420 >= 98304
#define NWARPS 16
#define CH     88                 // pairs per build chunk, 528 = 6*88
#define NCHUNK 6

__device__ float g_WS[4 * WS_FLOATS];
__device__ float g_WV[4 * WV_FLOATS];
__device__ unsigned short g_LUT[NPAIR];
__device__ float g_Xk[(size_t)EDIM * 4 * 128];

// ---------------------------------------------------------------------------
// Prep: blocks [0,1024) do weights, blocks [1024, 17408) do features.
// ---------------------------------------------------------------------------
__global__ void prep(const float* __restrict__ x,
                     const float* __restrict__ Ws, const float* __restrict__ Wf,
                     const float* __restrict__ Wn, const float* __restrict__ Wa) {
    int blk = blockIdx.x;
    if (blk < 1024) {
        int tid = blk * 128 + threadIdx.x;        // 0..131071
        int w = tid & 31;
        int v = (tid >> 5) & 31;
        int u = (tid >> 10) & 31;
        int t = tid >> 15;
        const float* Wt = (t == 0) ? Ws : (t == 1) ? Wf : (t == 2) ? Wn : Wa;
        const float norm = 0.022097086912079608f;   // 1/(32*sqrt(2))
        const float i3   = 0.5773502691896258f;     // 1/sqrt(3)

        float w2 = Wt[2*32768 + (u*32 + v)*32 + w];
        float w3 = Wt[3*32768 + (v*32 + u)*32 + w];
        g_WV[t*WV_FLOATS + u*1152 + w*36 + v] = norm * (w2 + w3);

        if (u <= v) {
            int p = ((u * (65 - u)) >> 1) + (v - u);
            float a0 = Wt[0*32768 + (u*32 + v)*32 + w];
            float a1 = Wt[1*32768 + (u*32 + v)*32 + w];
            if (u != v) {
                a0 += Wt[0*32768 + (v*32 + u)*32 + w];
                a1 += Wt[1*32768 + (v*32 + u)*32 + w];
            }
            int q  = p;
            int q2 = 528 + p;
            g_WS[t*WS_FLOATS + (q  >> 2)*128 + w*4 + (q  & 3)] = norm * a0;
            g_WS[t*WS_FLOATS + (q2 >> 2)*128 + w*4 + (q2 & 3)] = norm * i3 * a1;
            if (t == 0 && w == 0) g_LUT[p] = (unsigned short)(u | (v << 8));
        }
    } else {
        int b  = blk - 1024;     // 0..16383
        int ch = threadIdx.x;    // 0..127
        const float* xb = x + (size_t)b * 6 * 128 + ch;
        float xv[6];
        #pragma unroll
        for (int q = 0; q < 6; q++) xv[q] = xb[q * 128];
        float r0 = xv[0] + xv[1] + xv[2];
        float r1 = xv[3] + xv[4] + xv[5];
        float c0 = xv[0] + xv[3];
        float c1 = xv[1] + xv[4];
        float c2 = xv[2] + xv[5];
        float tot = r0 + r1;
        float* o = g_Xk + (size_t)b * 6 * 4 * 128 + ch;
        #pragma unroll
        for (int i = 0; i < 2; i++) {
            float ri = i ? r1 : r0;
            #pragma unroll
            for (int j = 0; j < 3; j++) {
                float cj = (j == 0) ? c0 : (j == 1) ? c1 : c2;
                float xs = xv[i*3 + j];
                float xf = (ri - xs) * 0.5f;
                float xn = (cj - xs);
                float xa = (tot - ri - cj + xs) * 0.5f;
                float* oe = o + (size_t)(i*3 + j) * 512;
                oe[0]   = xs;
                oe[128] = xf;
                oe[256] = xn;
                oe[384] = xa;
            }
        }
    }
}

// ---------------------------------------------------------------------------
// Main: 148 CTAs x 512 threads. Warp processes 4 elements at a time.
// ---------------------------------------------------------------------------
__global__ void __launch_bounds__(512, 1) petp_main(float* __restrict__ out) {
    extern __shared__ float sm[];
    float* Wsm     = sm;                                   // 36864 floats max
    float* PGall   = sm + WV_FLOATS;                       // 16 * 4 * 88
    float* featall = PGall + NWARPS * 4 * CH;              // 16 * 512
    float* S4all   = featall + NWARPS * 512;               // 16 * 128
    unsigned short* LUTs = (unsigned short*)(S4all + NWARPS * 128);  // 528 u16

    const int tid  = threadIdx.x;
    const int warp = tid >> 5;
    const int lane = tid & 31;
    float* PG   = PGall   + warp * 4 * CH;
    float* feat = featall + warp * 512;
    float* S4   = S4all   + warp * 128;

    for (int i = tid; i < NPAIR; i += 512) LUTs[i] = g_LUT[i];

    const int base  = blockIdx.x * EPC;
    const int count = (EPC < EDIM - base) ? EPC : (EDIM - base);

    for (int t = 0; t < 4; ++t) {
        // ================= scalar phase =================
        __syncthreads();
        {
            const float4* src = (const float4*)(g_WS + t * WS_FLOATS);
            float4* dst = (float4*)Wsm;
            for (int i = tid; i < WS_FLOATS/4; i += 512) dst[i] = src[i];
        }
        __syncthreads();

        for (int g = warp; g * 4 < count; g += NWARPS) {
            const int e0 = base + g * 4;
            #pragma unroll
            for (int e = 0; e < 4; ++e) {
                int ee = e0 + e; if (ee >= EDIM) ee = EDIM - 1;
                ((float4*)(feat + e*128))[lane] =
                    ((const float4*)(g_Xk + ((size_t)ee*4 + t)*128))[lane];
            }
            __syncwarp();

            float a0_0=0.f,a0_1=0.f,a0_2=0.f,a0_3=0.f;
            float a1_0=0.f,a1_1=0.f,a1_2=0.f,a1_3=0.f;

            #pragma unroll 1
            for (int h = 0; h < 2; ++h) {
                #pragma unroll 1
                for (int c = 0; c < NCHUNK; ++c) {
                    const int p0 = c * CH;
                    // ---- build chunk ----
                    for (int i = lane; i < CH; i += 32) {
                        unsigned int uv = LUTs[p0 + i];
                        int u = uv & 255, v = uv >> 8;
                        if (h == 0) {
                            #pragma unroll
                            for (int e = 0; e < 4; ++e)
                                PG[e*CH + i] = feat[e*128 + u] * feat[e*128 + v];
                        } else {
                            #pragma unroll
                            for (int e = 0; e < 4; ++e) {
                                const float* fu = feat + e*128 + 32 + u*3;
                                const float* fv = feat + e*128 + 32 + v*3;
                                PG[e*CH + i] = fmaf(fu[0], fv[0],
                                                fmaf(fu[1], fv[1], fu[2]*fv[2]));
                            }
                        }
                    }
                    __syncwarp();
                    // ---- contract chunk ----
                    const int pb0 = (h * 528 + p0) >> 2;
                    const float4* W4  = (const float4*)Wsm;
                    const float4* P0  = (const float4*)(PG);
                    const float4* P1  = (const float4*)(PG + CH);
                    const float4* P2  = (const float4*)(PG + 2*CH);
                    const float4* P3  = (const float4*)(PG + 3*CH);
                    #pragma unroll 2
                    for (int b = 0; b < CH/4; ++b) {
                        float4 wv = W4[(pb0 + b)*32 + lane];
                        float4 f0 = P0[b], f1 = P1[b], f2 = P2[b], f3 = P3[b];
                        a0_0 = fmaf(wv.x, f0.x, a0_0); a1_0 = fmaf(wv.y, f0.y, a1_0);
                        a0_0 = fmaf(wv.z, f0.z, a0_0); a1_0 = fmaf(wv.w, f0.w, a1_0);
                        a0_1 = fmaf(wv.x, f1.x, a0_1); a1_1 = fmaf(wv.y, f1.y, a1_1);
                        a0_1 = fmaf(wv.z, f1.z, a0_1); a1_1 = fmaf(wv.w, f1.w, a1_1);
                        a0_2 = fmaf(wv.x, f2.x, a0_2); a1_2 = fmaf(wv.y, f2.y, a1_2);
                        a0_2 = fmaf(wv.z, f2.z, a0_2); a1_2 = fmaf(wv.w, f2.w, a1_2);
                        a0_3 = fmaf(wv.x, f3.x, a0_3); a1_3 = fmaf(wv.y, f3.y, a1_3);
                        a0_3 = fmaf(wv.z, f3.z, a0_3); a1_3 = fmaf(wv.w, f3.w, a1_3);
                    }
                    __syncwarp();
                }
            }
            float ys[4] = { a0_0 + a1_0, a0_1 + a1_1, a0_2 + a1_2, a0_3 + a1_3 };
            #pragma unroll
            for (int e = 0; e < 4; ++e) {
                if (g*4 + e < count) {
                    float* o = out + (size_t)(e0 + e)*128 + lane;
                    *o = (t == 0) ? ys[e] : (*o + ys[e]);
                }
            }
        }

        // ================= vector phase =================
        __syncthreads();
        {
            const float4* src = (const float4*)(g_WV + t * WV_FLOATS);
            float4* dst = (float4*)Wsm;
            for (int i = tid; i < WV_FLOATS/4; i += 512) dst[i] = src[i];
        }
        __syncthreads();

        for (int g = warp; g * 4 < count; g += NWARPS) {
            const int e0 = base + g * 4;
            #pragma unroll
            for (int e = 0; e < 4; ++e) {
                int ee = e0 + e; if (ee >= EDIM) ee = EDIM - 1;
                ((float4*)(feat + e*128))[lane] =
                    ((const float4*)(g_Xk + ((size_t)ee*4 + t)*128))[lane];
            }
            __syncwarp();
            #pragma unroll
            for (int e = 0; e < 4; ++e) S4[lane*4 + e] = feat[e*128 + lane];
            __syncwarp();

            float y0[4] = {0,0,0,0}, y1[4] = {0,0,0,0}, y2[4] = {0,0,0,0};

            #pragma unroll 1
            for (int vc = 0; vc < 32; vc += 8) {
                float cacc[8][4];
                #pragma unroll
                for (int j = 0; j < 8; ++j)
                    #pragma unroll
                    for (int e = 0; e < 4; ++e) cacc[j][e] = 0.f;

                #pragma unroll 4
                for (int u = 0; u < 32; ++u) {
                    float4 s4v = *((const float4*)(S4 + u*4));                     // uniform
                    float4 wA  = *((const float4*)(Wsm + u*1152 + lane*36 + vc));
                    float4 wB  = *((const float4*)(Wsm + u*1152 + lane*36 + vc + 4));
                    float sA[4] = { s4v.x, s4v.y, s4v.z, s4v.w };
                    float wAa[4] = { wA.x, wA.y, wA.z, wA.w };
                    float wBa[4] = { wB.x, wB.y, wB.z, wB.w };
                    #pragma unroll
                    for (int j = 0; j < 4; ++j)
                        #pragma unroll
                        for (int e = 0; e < 4; ++e) {
                            cacc[j][e]   = fmaf(wAa[j], sA[e], cacc[j][e]);
                            cacc[4+j][e] = fmaf(wBa[j], sA[e], cacc[4+j][e]);
                        }
                }
                #pragma unroll
                for (int j = 0; j < 8; ++j) {
                    const int v = vc + j;
                    #pragma unroll
                    for (int e = 0; e < 4; ++e) {
                        float cv = cacc[j][e];
                        const float* fv = feat + e*128 + 32 + v*3;   // uniform
                        y0[e] = fmaf(cv, fv[0], y0[e]);
                        y1[e] = fmaf(cv, fv[1], y1[e]);
                        y2[e] = fmaf(cv, fv[2], y2[e]);
                    }
                }
            }
            #pragma unroll
            for (int e = 0; e < 4; ++e) {
                if (g*4 + e < count) {
                    float* o = out + (size_t)(e0 + e)*128 + 32 + lane*3;
                    if (t == 0) { o[0] = y0[e];  o[1] = y1[e];  o[2] = y2[e]; }
                    else        { o[0] += y0[e]; o[1] += y1[e]; o[2] += y2[e]; }
                }
            }
        }
    }
}

// ---------------------------------------------------------------------------
extern "C" void kernel_launch(void* const* d_in, const int* in_sizes, int n_in,
                              void* d_out, int out_size) {
    const float* x  = (const float*)d_in[0];
    const float* Ws = (const float*)d_in[1];
    const float* Wf = (const float*)d_in[2];
    const float* Wn = (const float*)d_in[3];
    const float* Wa = (const float*)d_in[4];

    const int smem_floats = WV_FLOATS + NWARPS*4*CH + NWARPS*512 + NWARPS*128 + 264;
    const int smem_bytes  = smem_floats * 4;   // ~212 KB
    cudaFuncSetAttribute(petp_main, cudaFuncAttributeMaxDynamicSharedMemorySize, smem_bytes);

    prep<<<17408, 128>>>(x, Ws, Wf, Wn, Wa);
    petp_main<<<NCTA, 512, smem_bytes>>>((float*)d_out);
}